// round 2
// baseline (speedup 1.0000x reference)
#include <cuda_runtime.h>
#include <cstdint>

// LIFNeuron dopri5 — Round 2: packed fp32x2 FFMA (Blackwell FFMA2).
// Each lane owns output-column pair (j, j+32); z/g accumulators are f32x2.
// Weights pair-interleaved in SMEM, stage input duplicated {v,v} so both
// FMA2 operands come straight from ld.shared.v2.u64 (no packing ALU).
// Bitwise identical fp32 math to the R1 kernel (rel_err was exactly 0).

#define NWARP 8
#define R 8
#define NTHREADS (NWARP * 32)
#define WSP 132              // paired-weight row stride in floats (128 data + 4 pad)
#define ROWS_PER_BLOCK (NWARP * R)

#define HC(x) (0.125f * (float)(x))   // h * fp32(a), exact (h = 2^-3)

typedef unsigned long long u64;

__device__ __forceinline__ u64 fma2(u64 a, u64 b, u64 c) {
    u64 d;
    asm("fma.rn.f32x2 %0, %1, %2, %3;" : "=l"(d) : "l"(a), "l"(b), "l"(c));
    return d;
}
__device__ __forceinline__ u64 pack2(float lo, float hi) {
    u64 r;
    asm("mov.b64 %0, {%1, %2};" : "=l"(r) : "f"(lo), "f"(hi));
    return r;
}
__device__ __forceinline__ void unpack2(u64 v, float& lo, float& hi) {
    asm("mov.b64 {%0, %1}, %2;" : "=f"(lo), "=f"(hi) : "l"(v));
}
__device__ __forceinline__ u64 dup2(float v) { return pack2(v, v); }

// 16B shared vector load as two u64 halves (maps to LDS.128, operands pre-paired)
__device__ __forceinline__ void lds2(uint32_t addr, u64& a, u64& b) {
    asm("ld.shared.v2.u64 {%0, %1}, [%2];" : "=l"(a), "=l"(b) : "r"(addr));
}
__device__ __forceinline__ void lds2v(uint32_t addr, u64& a, u64& b) {
    asm volatile("ld.shared.v2.u64 {%0, %1}, [%2];" : "=l"(a), "=l"(b) : "r"(addr));
}
__device__ __forceinline__ void sts_dup(uint32_t addr, float v) {
    asm volatile("st.shared.v2.f32 [%0], {%1, %2};" :: "r"(addr), "f"(v), "f"(v));
}

__device__ __forceinline__ float gelu_f(float z) {
    return 0.5f * z * (1.0f + erff(z * 0.70710678118654752440f));
}
__device__ __forceinline__ float timefac_f(float g) {
    float e = expf(-g);
    float s = __frcp_rn(1.0f + e);
    return __frcp_rn(1.0f + s);
}

// k = f(xi) for R rows. xi[r] is this lane's (col lane, col lane+32) pair.
__device__ __forceinline__ void eval_f(
    uint32_t swz, uint32_t sgz, uint32_t sxb, int lane,
    float bg0, float bg1, const u64* __restrict__ xi, u64* __restrict__ o)
{
    __syncwarp();
    #pragma unroll
    for (int r = 0; r < R; r++) {
        float lo, hi; unpack2(xi[r], lo, hi);
        sts_dup(sxb + r * 512 + lane * 8,        lo);   // col = lane
        sts_dup(sxb + r * 512 + lane * 8 + 256,  hi);   // col = lane+32
    }
    __syncwarp();

    u64 zp[R], gp[R];
    #pragma unroll
    for (int r = 0; r < R; r++) { zp[r] = 0ull; gp[r] = 0ull; }

    #pragma unroll 8
    for (int q = 0; q < 32; q++) {           // 2 k's per iteration
        u64 wza, wzb, wga, wgb;
        lds2(swz + q * 16, wza, wzb);        // {W[2q][j],W[2q][j+32]},{W[2q+1][..]}
        lds2(sgz + q * 16, wga, wgb);
        #pragma unroll
        for (int r = 0; r < R; r++) {
            u64 xa, xb;                       // {v2q,v2q},{v2q+1,v2q+1} broadcast
            lds2v(sxb + r * 512 + q * 16, xa, xb);
            zp[r] = fma2(xa, wza, zp[r]);
            zp[r] = fma2(xb, wzb, zp[r]);
            gp[r] = fma2(xa, wga, gp[r]);
            gp[r] = fma2(xb, wgb, gp[r]);
        }
    }

    #pragma unroll
    for (int r = 0; r < R; r++) {
        float z0, z1, g0, g1;
        unpack2(zp[r], z0, z1);
        unpack2(gp[r], g0, g1);
        o[r] = pack2(gelu_f(z0) * timefac_f(g0 + bg0),
                     gelu_f(z1) * timefac_f(g1 + bg1));
    }
}

__global__ __launch_bounds__(NTHREADS, 1)
void lif_dopri5_kernel(const float* __restrict__ xin,
                       const float* __restrict__ W,
                       const float* __restrict__ Wg,
                       const float* __restrict__ bgp,
                       float* __restrict__ out,
                       int batch)
{
    __shared__ __align__(16) float sWp[32 * WSP];
    __shared__ __align__(16) float sGp[32 * WSP];
    __shared__ __align__(16) float sx[NWARP][R][128];   // duplicated stage inputs

    const int tid = threadIdx.x;
    // pair-interleave: sWp[jj*WSP + 2k + hi] = W[k][jj + 32*hi]
    for (int i = tid; i < 4096; i += NTHREADS) {
        int k = i >> 6, j = i & 63;
        int jj = j & 31, hi = j >> 5;
        sWp[jj * WSP + 2 * k + hi] = W[i];
        sGp[jj * WSP + 2 * k + hi] = Wg[i];
    }
    __syncthreads();

    const int warp = tid >> 5;
    const int lane = tid & 31;

    const uint32_t swz = (uint32_t)__cvta_generic_to_shared(sWp + lane * WSP);
    const uint32_t sgz = (uint32_t)__cvta_generic_to_shared(sGp + lane * WSP);
    const uint32_t sxb = (uint32_t)__cvta_generic_to_shared(&sx[warp][0][0]);

    const int row0 = (blockIdx.x * NWARP + warp) * R;
    if (row0 >= batch) return;

    const float bg0 = bgp[lane];
    const float bg1 = bgp[lane + 32];

    u64 xp[R];
    #pragma unroll
    for (int r = 0; r < R; r++) {
        int rr = (row0 + r < batch) ? (row0 + r) : (batch - 1);
        xp[r] = pack2(xin[rr * 64 + lane], xin[rr * 64 + lane + 32]);
    }

    // dopri5 tableau * h, packed {c,c}.  B5[1]==0, B5[6]==0 (k7 dead).
    const u64 A10 = dup2(HC(1.0 / 5.0));
    const u64 A20 = dup2(HC(3.0 / 40.0)),       A21 = dup2(HC(9.0 / 40.0));
    const u64 A30 = dup2(HC(44.0 / 45.0)),      A31 = dup2(HC(-56.0 / 15.0)),
              A32 = dup2(HC(32.0 / 9.0));
    const u64 A40 = dup2(HC(19372.0 / 6561.0)), A41 = dup2(HC(-25360.0 / 2187.0)),
              A42 = dup2(HC(64448.0 / 6561.0)), A43 = dup2(HC(-212.0 / 729.0));
    const u64 A50 = dup2(HC(9017.0 / 3168.0)),  A51 = dup2(HC(-355.0 / 33.0)),
              A52 = dup2(HC(46732.0 / 5247.0)), A53 = dup2(HC(49.0 / 176.0)),
              A54 = dup2(HC(-5103.0 / 18656.0));
    const u64 B0 = dup2(HC(35.0 / 384.0)),  B2 = dup2(HC(500.0 / 1113.0)),
              B3 = dup2(HC(125.0 / 192.0)), B4 = dup2(HC(-2187.0 / 6784.0)),
              B5c = dup2(HC(11.0 / 84.0));

    for (int step = 0; step < 8; step++) {
        u64 k1[R], k2[R], k3[R], k4[R], k5[R], k6[R], xi[R];

        eval_f(swz, sgz, sxb, lane, bg0, bg1, xp, k1);

        #pragma unroll
        for (int r = 0; r < R; r++) xi[r] = fma2(A10, k1[r], xp[r]);
        eval_f(swz, sgz, sxb, lane, bg0, bg1, xi, k2);

        #pragma unroll
        for (int r = 0; r < R; r++) {
            u64 a = fma2(A20, k1[r], xp[r]);
            xi[r] = fma2(A21, k2[r], a);
        }
        eval_f(swz, sgz, sxb, lane, bg0, bg1, xi, k3);

        #pragma unroll
        for (int r = 0; r < R; r++) {
            u64 a = fma2(A30, k1[r], xp[r]);
            a = fma2(A31, k2[r], a);
            xi[r] = fma2(A32, k3[r], a);
        }
        eval_f(swz, sgz, sxb, lane, bg0, bg1, xi, k4);

        #pragma unroll
        for (int r = 0; r < R; r++) {
            u64 a = fma2(A40, k1[r], xp[r]);
            a = fma2(A41, k2[r], a);
            a = fma2(A42, k3[r], a);
            xi[r] = fma2(A43, k4[r], a);
        }
        eval_f(swz, sgz, sxb, lane, bg0, bg1, xi, k5);

        #pragma unroll
        for (int r = 0; r < R; r++) {
            u64 a = fma2(A50, k1[r], xp[r]);
            a = fma2(A51, k2[r], a);
            a = fma2(A52, k3[r], a);
            a = fma2(A53, k4[r], a);
            xi[r] = fma2(A54, k5[r], a);
        }
        eval_f(swz, sgz, sxb, lane, bg0, bg1, xi, k6);

        #pragma unroll
        for (int r = 0; r < R; r++) {
            u64 a = fma2(B0, k1[r], xp[r]);
            a = fma2(B2, k3[r], a);
            a = fma2(B3, k4[r], a);
            a = fma2(B4, k5[r], a);
            xp[r] = fma2(B5c, k6[r], a);
        }
    }

    #pragma unroll
    for (int r = 0; r < R; r++) {
        int rr = row0 + r;
        if (rr < batch) {
            float lo, hi; unpack2(xp[r], lo, hi);
            out[rr * 64 + lane]      = ((lo - 0.3f) > 0.0f) ? 1.0f : 0.0f;
            out[rr * 64 + lane + 32] = ((hi - 0.3f) > 0.0f) ? 1.0f : 0.0f;
        }
    }
}

extern "C" void kernel_launch(void* const* d_in, const int* in_sizes, int n_in,
                              void* d_out, int out_size)
{
    const float* x  = (const float*)d_in[0];   // [batch, 64]
    const float* W  = (const float*)d_in[1];   // [64, 64] ode_weight
    const float* Wg = (const float*)d_in[2];   // [64, 64] gate_w
    const float* bg = (const float*)d_in[3];   // [64]     gate_b
    float* out = (float*)d_out;

    int batch = in_sizes[0] / 64;
    int grid = (batch + ROWS_PER_BLOCK - 1) / ROWS_PER_BLOCK;

    lif_dopri5_kernel<<<grid, NTHREADS>>>(x, W, Wg, bg, out, batch);
}

// round 4
// speedup vs baseline: 1.6535x; 1.6535x over previous
#include <cuda_runtime.h>
#include <cstdint>

// LIFNeuron dopri5 via mma.sync tf32 (3xTF32 split) — R4.
// Warp-private 16-row tiles; per stage D[16x128] = Xi[16x64] @ [W|Wg].
// k1,k2,k_cur in per-warp SMEM; k3,k4,k5 in A-layout registers.

#define THREADS 256
#define BSTR 136            // B smem row stride (floats): (136k+n)%32 = (8k+n)%32, conflict-free
#define KSTR 68             // k-buffer row stride: (68r+c)%32 = (4r+c)%32, conflict-free

#define HC(x) (0.125f * (float)(x))

extern __shared__ float smf[];

__device__ __forceinline__ uint32_t tf32r(float a) {
    uint32_t r; asm("cvt.rna.tf32.f32 %0, %1;" : "=r"(r) : "f"(a)); return r;
}

__device__ __forceinline__ void mma8(float* d, const uint32_t* a, uint32_t b0, uint32_t b1) {
    asm volatile("mma.sync.aligned.m16n8k8.row.col.f32.tf32.tf32.f32 "
        "{%0,%1,%2,%3}, {%4,%5,%6,%7}, {%8,%9}, {%0,%1,%2,%3};"
        : "+f"(d[0]), "+f"(d[1]), "+f"(d[2]), "+f"(d[3])
        : "r"(a[0]), "r"(a[1]), "r"(a[2]), "r"(a[3]), "r"(b0), "r"(b1));
}

__device__ __forceinline__ float gelu_f(float z) {
    return 0.5f * z * (1.0f + erff(z * 0.70710678118654752440f));
}
__device__ __forceinline__ float timefac_f(float g) {
    float e = expf(-g);
    float s = __frcp_rn(1.0f + e);
    return __frcp_rn(1.0f + s);
}

__global__ __launch_bounds__(THREADS, 1)
void lif_hmma_kernel(const float* __restrict__ xin,
                     const float* __restrict__ W,
                     const float* __restrict__ Wg,
                     const float* __restrict__ bgp,
                     float* __restrict__ out,
                     int batch)
{
    float* Bh = smf;                        // [64][BSTR] tf32-hi of [W|Wg], cols 0-63 = W, 64-127 = Wg
    float* Bl = smf + 64 * BSTR;            // tf32-lo
    float* K1 = smf + 2 * 64 * BSTR;        // per-warp [16][KSTR]
    float* K2 = K1 + 8 * 16 * KSTR;
    float* SC = K2 + 8 * 16 * KSTR;
    float* BG = SC + 8 * 16 * KSTR;         // [64]

    const int tid = threadIdx.x;
    const int warp = tid >> 5, lane = tid & 31;
    const int r0 = lane >> 2;               // groupID: fragment row
    const int c0 = lane & 3;                // threadID-in-group

    // ---- init B (hi/lo split of W|Wg), bg, zero k-buffers ----
    for (int i = tid; i < 4096; i += THREADS) {
        int k = i >> 6, n = i & 63;
        float w = W[i], g = Wg[i];
        uint32_t wh = tf32r(w), gh = tf32r(g);
        Bh[k * BSTR + n]      = __uint_as_float(wh);
        Bl[k * BSTR + n]      = __uint_as_float(tf32r(w - __uint_as_float(wh)));
        Bh[k * BSTR + 64 + n] = __uint_as_float(gh);
        Bl[k * BSTR + 64 + n] = __uint_as_float(tf32r(g - __uint_as_float(gh)));
    }
    if (tid < 64) BG[tid] = bgp[tid];
    for (int i = tid; i < 3 * 8 * 16 * KSTR; i += THREADS) K1[i] = 0.0f;
    __syncthreads();

    float* k1w = K1 + warp * 16 * KSTR;
    float* k2w = K2 + warp * 16 * KSTR;
    float* scw = SC + warp * 16 * KSTR;

    const int rowbase = blockIdx.x * 128 + warp * 16;

    // x state in A-fragment layout: xA[h][m] = row (r0+8h), col (c0+4m)
    float xA[2][16];
    #pragma unroll
    for (int h = 0; h < 2; h++) {
        int rr = rowbase + r0 + 8 * h;
        if (rr >= batch) rr = batch - 1;
        #pragma unroll
        for (int m = 0; m < 16; m++)
            xA[h][m] = xin[(size_t)rr * 64 + c0 + 4 * m];
    }

    float k3A[2][16], k4A[2][16], k5A[2][16];
    #pragma unroll
    for (int h = 0; h < 2; h++)
        #pragma unroll
        for (int m = 0; m < 16; m++) { k3A[h][m] = 0.f; k4A[h][m] = 0.f; k5A[h][m] = 0.f; }

    const float B0c = HC(35.0/384.0), B2c = HC(500.0/1113.0), B3c = HC(125.0/192.0),
                B4c = HC(-2187.0/6784.0), B5c = HC(11.0/84.0);

    #pragma unroll 1
    for (int step = 0; step < 8; step++) {
        #pragma unroll 1
        for (int s = 0; s < 6; s++) {
            // stage coefficients (h pre-multiplied); zeros keep the build uniform
            float c1, c2, c3, c4, c5;
            switch (s) {
                case 0:  c1 = 0.f;                 c2 = 0.f;                   c3 = 0.f;                  c4 = 0.f;               c5 = 0.f; break;
                case 1:  c1 = HC(1.0/5.0);         c2 = 0.f;                   c3 = 0.f;                  c4 = 0.f;               c5 = 0.f; break;
                case 2:  c1 = HC(3.0/40.0);        c2 = HC(9.0/40.0);          c3 = 0.f;                  c4 = 0.f;               c5 = 0.f; break;
                case 3:  c1 = HC(44.0/45.0);       c2 = HC(-56.0/15.0);        c3 = HC(32.0/9.0);         c4 = 0.f;               c5 = 0.f; break;
                case 4:  c1 = HC(19372.0/6561.0);  c2 = HC(-25360.0/2187.0);   c3 = HC(64448.0/6561.0);   c4 = HC(-212.0/729.0);  c5 = 0.f; break;
                default: c1 = HC(9017.0/3168.0);   c2 = HC(-355.0/33.0);       c3 = HC(46732.0/5247.0);   c4 = HC(49.0/176.0);    c5 = HC(-5103.0/18656.0); break;
            }

            // ---- build xi in A layout, split to tf32 hi/lo ----
            uint32_t Ahi[2][16], Alo[2][16];
            #pragma unroll
            for (int h = 0; h < 2; h++) {
                const int ro = (r0 + 8 * h) * KSTR + c0;
                #pragma unroll
                for (int m = 0; m < 16; m++) {
                    const int off = ro + 4 * m;
                    float acc = xA[h][m];
                    acc = fmaf(c1, k1w[off], acc);
                    acc = fmaf(c2, k2w[off], acc);
                    acc = fmaf(c3, k3A[h][m], acc);
                    acc = fmaf(c4, k4A[h][m], acc);
                    acc = fmaf(c5, k5A[h][m], acc);
                    uint32_t hb = tf32r(acc);
                    Ahi[h][m] = hb;
                    Alo[h][m] = tf32r(acc - __uint_as_float(hb));
                }
            }

            float* dst = (s == 0) ? k1w : (s == 1) ? k2w : scw;

            // ---- MMA: 4 groups of 4 n-tiles {z j, g j, z j+1, g j+1} ----
            #pragma unroll 1
            for (int grp = 0; grp < 4; grp++) {
                const int nb0 = 16 * grp;         // z tile j = 2*grp
                const int nb1 = 64 + nb0;         // paired g tile
                const int nb2 = nb0 + 8;          // z tile j+1
                const int nb3 = 64 + nb2;

                float d0[4] = {0,0,0,0}, d1[4] = {0,0,0,0};
                float d2[4] = {0,0,0,0}, d3[4] = {0,0,0,0};

                #pragma unroll
                for (int kc = 0; kc < 8; kc++) {
                    const int bb = (kc * 8 + c0) * BSTR + r0;
                    uint32_t bh0_0 = __float_as_uint(Bh[bb + nb0]);
                    uint32_t bh1_0 = __float_as_uint(Bh[bb + 4 * BSTR + nb0]);
                    uint32_t bl0_0 = __float_as_uint(Bl[bb + nb0]);
                    uint32_t bl1_0 = __float_as_uint(Bl[bb + 4 * BSTR + nb0]);
                    uint32_t bh0_1 = __float_as_uint(Bh[bb + nb1]);
                    uint32_t bh1_1 = __float_as_uint(Bh[bb + 4 * BSTR + nb1]);
                    uint32_t bl0_1 = __float_as_uint(Bl[bb + nb1]);
                    uint32_t bl1_1 = __float_as_uint(Bl[bb + 4 * BSTR + nb1]);
                    uint32_t bh0_2 = __float_as_uint(Bh[bb + nb2]);
                    uint32_t bh1_2 = __float_as_uint(Bh[bb + 4 * BSTR + nb2]);
                    uint32_t bl0_2 = __float_as_uint(Bl[bb + nb2]);
                    uint32_t bl1_2 = __float_as_uint(Bl[bb + 4 * BSTR + nb2]);
                    uint32_t bh0_3 = __float_as_uint(Bh[bb + nb3]);
                    uint32_t bh1_3 = __float_as_uint(Bh[bb + 4 * BSTR + nb3]);
                    uint32_t bl0_3 = __float_as_uint(Bl[bb + nb3]);
                    uint32_t bl1_3 = __float_as_uint(Bl[bb + 4 * BSTR + nb3]);

                    uint32_t ah[4] = {Ahi[0][2*kc], Ahi[1][2*kc], Ahi[0][2*kc+1], Ahi[1][2*kc+1]};
                    uint32_t al[4] = {Alo[0][2*kc], Alo[1][2*kc], Alo[0][2*kc+1], Alo[1][2*kc+1]};

                    // pass HH
                    mma8(d0, ah, bh0_0, bh1_0);
                    mma8(d1, ah, bh0_1, bh1_1);
                    mma8(d2, ah, bh0_2, bh1_2);
                    mma8(d3, ah, bh0_3, bh1_3);
                    // pass HL
                    mma8(d0, ah, bl0_0, bl1_0);
                    mma8(d1, ah, bl0_1, bl1_1);
                    mma8(d2, ah, bl0_2, bl1_2);
                    mma8(d3, ah, bl0_3, bl1_3);
                    // pass LH
                    mma8(d0, al, bh0_0, bh1_0);
                    mma8(d1, al, bh0_1, bh1_1);
                    mma8(d2, al, bh0_2, bh1_2);
                    mma8(d3, al, bh0_3, bh1_3);
                }

                // ---- nonlinear k = gelu(z)*tf(g+bg), store D-layout to dst ----
                {
                    float bga = BG[nb0 + 2 * c0], bgb = BG[nb0 + 2 * c0 + 1];
                    float kv0 = gelu_f(d0[0]) * timefac_f(d1[0] + bga);
                    float kv1 = gelu_f(d0[1]) * timefac_f(d1[1] + bgb);
                    float kv2 = gelu_f(d0[2]) * timefac_f(d1[2] + bga);
                    float kv3 = gelu_f(d0[3]) * timefac_f(d1[3] + bgb);
                    *(float2*)&dst[r0 * KSTR + nb0 + 2 * c0]       = make_float2(kv0, kv1);
                    *(float2*)&dst[(r0 + 8) * KSTR + nb0 + 2 * c0] = make_float2(kv2, kv3);
                }
                {
                    float bga = BG[nb2 + 2 * c0], bgb = BG[nb2 + 2 * c0 + 1];
                    float kv0 = gelu_f(d2[0]) * timefac_f(d3[0] + bga);
                    float kv1 = gelu_f(d2[1]) * timefac_f(d3[1] + bgb);
                    float kv2 = gelu_f(d2[2]) * timefac_f(d3[2] + bga);
                    float kv3 = gelu_f(d2[3]) * timefac_f(d3[3] + bgb);
                    *(float2*)&dst[r0 * KSTR + nb2 + 2 * c0]       = make_float2(kv0, kv1);
                    *(float2*)&dst[(r0 + 8) * KSTR + nb2 + 2 * c0] = make_float2(kv2, kv3);
                }
            }

            __syncwarp();

            // ---- stage epilogue: pull scratch k into A-layout regs / final combine ----
            if (s == 2) {
                #pragma unroll
                for (int h = 0; h < 2; h++) {
                    const int ro = (r0 + 8 * h) * KSTR + c0;
                    #pragma unroll
                    for (int m = 0; m < 16; m++) k3A[h][m] = scw[ro + 4 * m];
                }
            } else if (s == 3) {
                #pragma unroll
                for (int h = 0; h < 2; h++) {
                    const int ro = (r0 + 8 * h) * KSTR + c0;
                    #pragma unroll
                    for (int m = 0; m < 16; m++) k4A[h][m] = scw[ro + 4 * m];
                }
            } else if (s == 4) {
                #pragma unroll
                for (int h = 0; h < 2; h++) {
                    const int ro = (r0 + 8 * h) * KSTR + c0;
                    #pragma unroll
                    for (int m = 0; m < 16; m++) k5A[h][m] = scw[ro + 4 * m];
                }
            } else if (s == 5) {
                #pragma unroll
                for (int h = 0; h < 2; h++) {
                    const int ro = (r0 + 8 * h) * KSTR + c0;
                    #pragma unroll
                    for (int m = 0; m < 16; m++) {
                        const int off = ro + 4 * m;
                        float a = xA[h][m];
                        a = fmaf(B0c, k1w[off], a);
                        a = fmaf(B2c, k3A[h][m], a);
                        a = fmaf(B3c, k4A[h][m], a);
                        a = fmaf(B4c, k5A[h][m], a);
                        xA[h][m] = fmaf(B5c, scw[off], a);
                    }
                }
            }
            __syncwarp();   // order reads above before next stage's buffer overwrites
        }
    }

    // ---- spike output ----
    #pragma unroll
    for (int h = 0; h < 2; h++) {
        int rr = rowbase + r0 + 8 * h;
        if (rr < batch) {
            #pragma unroll
            for (int m = 0; m < 16; m++)
                out[(size_t)rr * 64 + c0 + 4 * m] = ((xA[h][m] - 0.3f) > 0.0f) ? 1.0f : 0.0f;
        }
    }
}

extern "C" void kernel_launch(void* const* d_in, const int* in_sizes, int n_in,
                              void* d_out, int out_size)
{
    const float* x  = (const float*)d_in[0];   // [batch, 64]
    const float* W  = (const float*)d_in[1];   // [64, 64]
    const float* Wg = (const float*)d_in[2];   // [64, 64]
    const float* bg = (const float*)d_in[3];   // [64]
    float* out = (float*)d_out;

    const int smem_bytes = (2 * 64 * BSTR + 3 * 8 * 16 * KSTR + 64) * 4;
    cudaFuncSetAttribute(lif_hmma_kernel, cudaFuncAttributeMaxDynamicSharedMemorySize, smem_bytes);

    int batch = in_sizes[0] / 64;
    int grid = (batch + 127) / 128;
    lif_hmma_kernel<<<grid, THREADS, smem_bytes>>>(x, W, Wg, bg, out, batch);
}